// round 6
// baseline (speedup 1.0000x reference)
#include <cuda_runtime.h>
#include <cuda_bf16.h>

// Problem shape (fixed by reference setup_inputs)
#define B_DIM 32
#define C_DIM 512
#define HW    4096            // 64*64
#define KTOP  256             // 0.5 * C
#define NBC   (B_DIM * C_DIM) // 16384

// Scratch (no cudaMalloc allowed; zero-initialized at module load)
__device__ float g_ssq[NBC];            // per-(b,c) sum of targets^2 (ranking key)
__device__ float g_ssd[NBC];            // per-(b,c) sum of (in - tgt)^2
__device__ float g_batch[B_DIM];        // per-batch kept-ssd sums
__device__ unsigned int g_bdone[B_DIM]; // per-batch completion counters (self-reset)
__device__ unsigned int g_done2;        // batch-selection counter (self-reset)

// Release-scoped global atomicAdd: orders this thread's prior global stores
// before the increment WITHOUT a gpu-scope fence (no CCTL.IVALL / L1 flush —
// the R4 mistake). Returns the previous value.
__device__ __forceinline__ unsigned int atom_add_release(unsigned int* p, unsigned int v)
{
    unsigned int prev;
    asm volatile("atom.release.gpu.global.add.u32 %0, [%1], %2;"
                 : "=r"(prev) : "l"(p), "r"(v) : "memory");
    return prev;
}

// ---------------------------------------------------------------------------
// Single fused kernel.
// Phase 1 (all 16384 blocks): stream one (b,c) plane, block-reduce ssq/ssd,
//   store, then RELEASE-atomic bump of the per-batch counter. Identical load
//   path to the known 79.7us/85.7%-DRAM kernel; no fences, no L1 flushes.
// Phase 2 (the 512th block of each batch): rank-count top-k selection from
//   L2 (all reads via __ldcg so stale L1 is bypassed), fixed-order reduce
//   into g_batch[b], release-bump g_done2.
// Phase 3 (the 32nd selector): fixed-order 32-sum -> scalar. Counters reset
//   in-kernel so graph replays start clean. All reductions fixed-order ->
//   bitwise deterministic.
// ---------------------------------------------------------------------------
__global__ __launch_bounds__(256, 8) void fused_kernel(
    const float* __restrict__ inp,
    const float* __restrict__ tgt,
    float* __restrict__ out)
{
    const int bc = blockIdx.x;
    const int b  = bc >> 9;            // batch (512 channels per batch)
    const float4* __restrict__ ip =
        reinterpret_cast<const float4*>(inp + (size_t)bc * HW);
    const float4* __restrict__ tp =
        reinterpret_cast<const float4*>(tgt + (size_t)bc * HW);

    const int t = threadIdx.x;
    const int warp = t >> 5;
    const int lane = t & 31;

    // ---------------- Phase 1: streaming reduce (HBM-bound) ----------------
    float ssq = 0.0f;
    float ssd = 0.0f;

#pragma unroll
    for (int i = 0; i < 4; i++) {
        float4 a = ip[t + i * 256];
        float4 bb = tp[t + i * 256];
        ssq = fmaf(bb.x, bb.x, ssq);
        ssq = fmaf(bb.y, bb.y, ssq);
        ssq = fmaf(bb.z, bb.z, ssq);
        ssq = fmaf(bb.w, bb.w, ssq);
        float dx = a.x - bb.x;
        float dy = a.y - bb.y;
        float dz = a.z - bb.z;
        float dw = a.w - bb.w;
        ssd = fmaf(dx, dx, ssd);
        ssd = fmaf(dy, dy, ssd);
        ssd = fmaf(dz, dz, ssd);
        ssd = fmaf(dw, dw, ssd);
    }

#pragma unroll
    for (int off = 16; off > 0; off >>= 1) {
        ssq += __shfl_xor_sync(0xFFFFFFFFu, ssq, off);
        ssd += __shfl_xor_sync(0xFFFFFFFFu, ssd, off);
    }

    __shared__ float s_ssq[8];
    __shared__ float s_ssd[8];
    if (lane == 0) {
        s_ssq[warp] = ssq;
        s_ssd[warp] = ssd;
    }
    __syncthreads();

    __shared__ bool s_do_select;
    if (warp == 0) {
        float q = (lane < 8) ? s_ssq[lane] : 0.0f;
        float d = (lane < 8) ? s_ssd[lane] : 0.0f;
#pragma unroll
        for (int off = 4; off > 0; off >>= 1) {
            q += __shfl_xor_sync(0xFFFFFFFFu, q, off);
            d += __shfl_xor_sync(0xFFFFFFFFu, d, off);
        }
        if (lane == 0) {
            g_ssq[bc] = q;
            g_ssd[bc] = d;
            // release: data stores above are ordered before this increment
            unsigned int prev = atom_add_release(&g_bdone[b], 1u);
            s_do_select = (prev == C_DIM - 1);   // last block of batch b
        }
    }
    __syncthreads();

    if (!s_do_select) return;

    // ------------- Phase 2: this block selects top-k for batch b -----------
    // Read via .cg (L2-direct): every producer's release-atomic ordered its
    // stores into L2 before the counter reached 512, and .cg bypasses any
    // stale L1 lines. No fence needed.
    __shared__ float4 s_norm4[C_DIM / 4];   // 512 norms as 128 float4
    if (t < C_DIM / 4)
        s_norm4[t] = __ldcg(reinterpret_cast<const float4*>(g_ssq + b * C_DIM) + t);
    __syncthreads();

    const float* s_norm = reinterpret_cast<const float*>(s_norm4);
    const int c0 = t;           // channels t and t+256
    const int c1 = t + 256;
    const float v0 = s_norm[c0];
    const float v1 = s_norm[c1];

    int cnt0 = 0, cnt1 = 0;
#pragma unroll 4
    for (int j = 0; j < C_DIM / 4; j++) {
        float4 n = s_norm4[j];             // broadcast, conflict-free
        cnt0 += (n.x > v0) + (n.y > v0) + (n.z > v0) + (n.w > v0);
        cnt1 += (n.x > v1) + (n.y > v1) + (n.z > v1) + (n.w > v1);
    }

    float contrib = 0.0f;
    if (cnt0 < KTOP) contrib += __ldcg(g_ssd + b * C_DIM + c0);
    if (cnt1 < KTOP) contrib += __ldcg(g_ssd + b * C_DIM + c1);

#pragma unroll
    for (int off = 16; off > 0; off >>= 1)
        contrib += __shfl_xor_sync(0xFFFFFFFFu, contrib, off);

    __shared__ float s_p[8];
    if (lane == 0) s_p[warp] = contrib;
    __syncthreads();

    __shared__ bool s_do_final;
    if (t == 0) {
        float x = ((s_p[0] + s_p[1]) + (s_p[2] + s_p[3]))
                + ((s_p[4] + s_p[5]) + (s_p[6] + s_p[7]));
        g_batch[b] = x;
        g_bdone[b] = 0;                    // reset for next graph replay
        // release: g_batch[b] store ordered before this increment
        unsigned int prev2 = atom_add_release(&g_done2, 1u);
        s_do_final = (prev2 == B_DIM - 1);
    }
    __syncthreads();

    // ---------------- Phase 3: final scalar (fixed order) ------------------
    if (s_do_final && t == 0) {
        float total = 0.0f;
#pragma unroll
        for (int i = 0; i < B_DIM; i++)
            total += __ldcg(g_batch + i);  // L2-direct, publishers used release
        out[0] = total / ((float)HW * (float)(B_DIM * KTOP));
        g_done2 = 0;                       // reset for next graph replay
    }
}

extern "C" void kernel_launch(void* const* d_in, const int* in_sizes, int n_in,
                              void* d_out, int out_size)
{
    const float* inputs  = (const float*)d_in[0];
    const float* targets = (const float*)d_in[1];
    float* out = (float*)d_out;

    fused_kernel<<<NBC, 256>>>(inputs, targets, out);
}

// round 7
// speedup vs baseline: 1.1730x; 1.1730x over previous
#include <cuda_runtime.h>
#include <cuda_bf16.h>

// Problem shape (fixed by reference setup_inputs)
#define B_DIM 32
#define C_DIM 512
#define HW    4096            // 64*64
#define KTOP  256             // 0.5 * C
#define NBC   (B_DIM * C_DIM) // 16384
#define SEL_BLOCKS 128        // 32 batches x 4 channel groups

// Scratch (no cudaMalloc allowed; zero-initialized at module load)
__device__ float g_ssq[NBC];        // per-(b,c) sum of targets^2 (ranking key)
__device__ float g_ssd[NBC];        // per-(b,c) sum of (in - tgt)^2
__device__ float g_part[SEL_BLOCKS];
__device__ unsigned int g_done;     // self-resetting completion counter

// ---------------------------------------------------------------------------
// Kernel 1: streaming reduce, one block per (b,c) plane. Known-good R5 body
// (84.0us total), single change: __ldcs streaming loads (zero-reuse data,
// evict-first). No fences, no atomics (R4/R6 lesson: ANY blocking op at block
// exit delays CTA-slot recycling and starves chip MLP at the memory wall).
// ---------------------------------------------------------------------------
__global__ __launch_bounds__(256, 8) void bc_reduce_kernel(
    const float* __restrict__ inp,
    const float* __restrict__ tgt)
{
    const int bc = blockIdx.x;
    const float4* __restrict__ ip =
        reinterpret_cast<const float4*>(inp + (size_t)bc * HW);
    const float4* __restrict__ tp =
        reinterpret_cast<const float4*>(tgt + (size_t)bc * HW);

    const int t = threadIdx.x;

    float ssq = 0.0f;
    float ssd = 0.0f;

#pragma unroll
    for (int i = 0; i < 4; i++) {
        float4 a = __ldcs(ip + t + i * 256);
        float4 b = __ldcs(tp + t + i * 256);
        ssq = fmaf(b.x, b.x, ssq);
        ssq = fmaf(b.y, b.y, ssq);
        ssq = fmaf(b.z, b.z, ssq);
        ssq = fmaf(b.w, b.w, ssq);
        float dx = a.x - b.x;
        float dy = a.y - b.y;
        float dz = a.z - b.z;
        float dw = a.w - b.w;
        ssd = fmaf(dx, dx, ssd);
        ssd = fmaf(dy, dy, ssd);
        ssd = fmaf(dz, dz, ssd);
        ssd = fmaf(dw, dw, ssd);
    }

#pragma unroll
    for (int off = 16; off > 0; off >>= 1) {
        ssq += __shfl_xor_sync(0xFFFFFFFFu, ssq, off);
        ssd += __shfl_xor_sync(0xFFFFFFFFu, ssd, off);
    }

    __shared__ float s_ssq[8];
    __shared__ float s_ssd[8];
    const int warp = t >> 5;
    const int lane = t & 31;
    if (lane == 0) {
        s_ssq[warp] = ssq;
        s_ssd[warp] = ssd;
    }
    __syncthreads();

    if (warp == 0) {
        float q = (lane < 8) ? s_ssq[lane] : 0.0f;
        float d = (lane < 8) ? s_ssd[lane] : 0.0f;
#pragma unroll
        for (int off = 4; off > 0; off >>= 1) {
            q += __shfl_xor_sync(0xFFFFFFFFu, q, off);
            d += __shfl_xor_sync(0xFFFFFFFFu, d, off);
        }
        if (lane == 0) {
            g_ssq[bc] = q;
            g_ssd[bc] = d;
        }
    }

    __syncthreads();
    cudaTriggerProgrammaticLaunchCompletion();
}

// ---------------------------------------------------------------------------
// Kernel 2: fused select + final (PDL secondary). Change vs R5: the ssd value
// is loaded BEFORE the rank loop so its L2 latency hides under the 128
// compare iterations; likewise g_part is read before the final shuffles.
// Deterministic fixed-order reductions; g_done self-resets for graph replay.
// ---------------------------------------------------------------------------
__global__ __launch_bounds__(128) void select_final_kernel(float* __restrict__ out)
{
    // PDL: wait until the upstream grid's memory (g_ssq/g_ssd) is visible.
    cudaGridDependencySynchronize();

    __shared__ float4 s_norm4[C_DIM / 4];   // 512 norms as 128 float4
    __shared__ float  s_p[4];
    __shared__ bool   s_last;

    const int b = blockIdx.x >> 2;     // batch
    const int g = blockIdx.x & 3;      // channel group (128 channels)
    const int t = threadIdx.x;
    const int warp = t >> 5;
    const int lane = t & 31;
    const int c = g * 128 + t;         // this thread's channel

    // Issue BOTH global loads up front: ssd's latency hides under the rank loop.
    const float my_ssd = g_ssd[b * C_DIM + c];
    s_norm4[t] = reinterpret_cast<const float4*>(g_ssq + b * C_DIM)[t];
    __syncthreads();

    const float v = reinterpret_cast<const float*>(s_norm4)[c];

    int cnt = 0;
#pragma unroll 4
    for (int j = 0; j < C_DIM / 4; j++) {
        float4 n = s_norm4[j];         // broadcast, conflict-free
        cnt += (n.x > v) ? 1 : 0;
        cnt += (n.y > v) ? 1 : 0;
        cnt += (n.z > v) ? 1 : 0;
        cnt += (n.w > v) ? 1 : 0;
    }

    float contrib = (cnt < KTOP) ? my_ssd : 0.0f;

#pragma unroll
    for (int off = 16; off > 0; off >>= 1)
        contrib += __shfl_xor_sync(0xFFFFFFFFu, contrib, off);
    if (lane == 0) s_p[warp] = contrib;
    __syncthreads();

    if (t == 0) {
        float x = (s_p[0] + s_p[1]) + (s_p[2] + s_p[3]);
        g_part[blockIdx.x] = x;
        __threadfence();
        unsigned int prev = atomicAdd(&g_done, 1u);
        s_last = (prev == SEL_BLOCKS - 1);
    }
    __syncthreads();

    if (s_last) {
        __threadfence();               // acquire: make all g_part writes visible
        float x = g_part[t];           // 128 partials, one per thread
#pragma unroll
        for (int off = 16; off > 0; off >>= 1)
            x += __shfl_xor_sync(0xFFFFFFFFu, x, off);

        __shared__ float s_f[4];
        if (lane == 0) s_f[warp] = x;
        __syncthreads();
        if (t == 0) {
            float total = (s_f[0] + s_f[1]) + (s_f[2] + s_f[3]);
            out[0] = total / ((float)HW * (float)(B_DIM * KTOP));
            g_done = 0;                // reset for next graph replay
        }
    }
}

extern "C" void kernel_launch(void* const* d_in, const int* in_sizes, int n_in,
                              void* d_out, int out_size)
{
    const float* inputs  = (const float*)d_in[0];
    const float* targets = (const float*)d_in[1];
    float* out = (float*)d_out;

    bc_reduce_kernel<<<NBC, 256>>>(inputs, targets);

    // Dependent launch with programmatic stream serialization (PDL):
    // select_final_kernel's launch/prologue overlaps bc_reduce's tail.
    cudaLaunchConfig_t cfg = {};
    cfg.gridDim  = dim3(SEL_BLOCKS);
    cfg.blockDim = dim3(128);
    cfg.dynamicSmemBytes = 0;
    cfg.stream = 0;   // legacy default stream (same as <<<>>> above)
    cudaLaunchAttribute attrs[1];
    attrs[0].id = cudaLaunchAttributeProgrammaticStreamSerialization;
    attrs[0].val.programmaticStreamSerializationAllowed = 1;
    cfg.attrs = attrs;
    cfg.numAttrs = 1;
    cudaLaunchKernelEx(&cfg, select_final_kernel, out);
}